// round 13
// baseline (speedup 1.0000x reference)
#include <cuda_runtime.h>
#include <stdint.h>

#define NTOK 65536
#define DIM  512
#define NQ   (NTOK * DIM)
#define DELTA 2e-6f

typedef unsigned long long u64;

// ====================== scratch (device globals) ======================
__device__ float g_tf[NQ];
__device__ float g_ef[NQ];
__device__ float g_df[NQ];
__device__ float g_res[NQ];
__device__ float g_fhi[3 * NQ], g_flo[3 * NQ];        // tf, ef, df hi/lo
__device__ float g_reshi[NQ], g_reslo[NQ];
__device__ float g_cbhi[1792 * 512], g_cblo[1792 * 512];  // tcb@0, ecb@512, cb0@768, cb1@1280
__device__ float g_sqA[4 * NTOK];
__device__ float g_cbsq[1792];
__device__ int   g_idx[4 * NTOK];
__device__ u64   g_top2[NTOK * 6];                 // per token: 2 chunks x (L1,H1,L2)
__device__ int   g_nflag[4];
__device__ int   g_flagged[4][NTOK];
__device__ float g_P[1792 * DIM];
__device__ double g_losspart[4096];

// ====================== helpers ======================
__device__ __forceinline__ uint32_t smem_to_u32(const void* p) {
    uint32_t a;
    asm("{ .reg .u64 t; cvta.to.shared.u64 t, %1; cvt.u32.u64 %0, t; }" : "=r"(a) : "l"(p));
    return a;
}
__device__ __forceinline__ float to_tf32(float f) {
    float r;
    asm("cvt.rna.tf32.f32 %0, %1;" : "=f"(r) : "f"(f));
    return r;
}
#define CP_ASYNC(dst, src) \
    asm volatile("cp.async.cg.shared.global [%0], [%1], 16;" :: "r"(dst), "l"(src) : "memory")
#define CP_COMMIT() asm volatile("cp.async.commit_group;" ::: "memory")
#define CP_WAIT1()  asm volatile("cp.async.wait_group 1;" ::: "memory")

__device__ __forceinline__ void mma_tf32_16n8k8(float c[4], const uint32_t a[4], const uint32_t b[2]) {
    asm volatile("mma.sync.aligned.m16n8k8.row.col.f32.tf32.tf32.f32 "
                 "{%0,%1,%2,%3}, {%4,%5,%6,%7}, {%8,%9}, {%0,%1,%2,%3};"
                 : "+f"(c[0]), "+f"(c[1]), "+f"(c[2]), "+f"(c[3])
                 : "r"(a[0]), "r"(a[1]), "r"(a[2]), "r"(a[3]), "r"(b[0]), "r"(b[1]));
}

__device__ __forceinline__ u64 umin64_(u64 a, u64 b) { return a < b ? a : b; }

// push candidate (L,H) into (L1,H1,L2) [top-2 by L, H carried with winner]
__device__ __forceinline__ void top2_push(u64& L1, u64& H1, u64& L2, u64 L, u64 H) {
    if (L < L1) { L2 = L1; L1 = L; H1 = H; } else if (L < L2) { L2 = L; }
}
// merge another triple in
__device__ __forceinline__ void top2_mergeT(u64& L1, u64& H1, u64& L2, u64 l1, u64 h1, u64 l2) {
    if (l1 < L1) { L2 = umin64_(L1, l2); L1 = l1; H1 = h1; }
    else         { L2 = umin64_(l1, L2); }
}

// ====================== VQ distance GEMM, 3xTF32 split (mma.sync) ======================
// BM=128, BN=256, BK=16. 8 warps (2m x 4n), warp tile 64x64.
// Interval top-2 epilogue: dlo/dhi = fl(fl(Asq+cbsq) - 2(dot +/- DELTA));
// per-token (L1,H1,L2) -> gtop2[token*6 + chunk*3 ...].
#define STG_FLOATS 15360
#define AOFF(arr)  ((arr) * 2560)
#define BOFF(arr)  (5120 + (arr) * 5120)
#define GEMM_SMEM  (2 * STG_FLOATS * 4)       // 122880 bytes

__global__ __launch_bounds__(256, 1)
void vq3t(const float* __restrict__ Ahi, const float* __restrict__ Alo,
          const float* __restrict__ Bhi, const float* __restrict__ Blo,
          const float* __restrict__ Asq, const float* __restrict__ cbsq,
          u64* __restrict__ gtop2)
{
    extern __shared__ float sm[];
    const uint32_t smu = smem_to_u32(sm);
    const int tid  = threadIdx.x;
    const int lane = tid & 31, wid = tid >> 5;
    const int wm = wid >> 2, wn = wid & 3;
    const int bm = blockIdx.y * 128, bn = blockIdx.x * 256;
    const int fr = lane >> 2, fc = lane & 3;

    const int aRow = tid >> 1, aQ = (tid & 1) * 2;
    const int bRow = tid;
    const float* gAhi = Ahi + (size_t)(bm + aRow) * 512 + aQ * 4;
    const float* gAlo = Alo + (size_t)(bm + aRow) * 512 + aQ * 4;
    const float* gBhi = Bhi + (size_t)(bn + bRow) * 512;
    const float* gBlo = Blo + (size_t)(bn + bRow) * 512;
    const uint32_t dAhi = smu + (uint32_t)(AOFF(0) + aRow * 20 + aQ * 4) * 4u;
    const uint32_t dAlo = smu + (uint32_t)(AOFF(1) + aRow * 20 + aQ * 4) * 4u;
    const uint32_t dBhi = smu + (uint32_t)(BOFF(0) + bRow * 20) * 4u;
    const uint32_t dBlo = smu + (uint32_t)(BOFF(1) + bRow * 20) * 4u;
    const uint32_t stgB = STG_FLOATS * 4u;

#pragma unroll
    for (int s = 0; s < 2; s++) {
        const uint32_t so = s * stgB;
        const int ko = s * 16;
        CP_ASYNC(dAhi + so,      gAhi + ko);
        CP_ASYNC(dAhi + so + 16, gAhi + ko + 4);
        CP_ASYNC(dAlo + so,      gAlo + ko);
        CP_ASYNC(dAlo + so + 16, gAlo + ko + 4);
#pragma unroll
        for (int q = 0; q < 4; q++) {
            CP_ASYNC(dBhi + so + q * 16, gBhi + ko + q * 4);
            CP_ASYNC(dBlo + so + q * 16, gBlo + ko + q * 4);
        }
        CP_COMMIT();
    }

    float acc[4][8][4];
#pragma unroll
    for (int mi = 0; mi < 4; mi++)
#pragma unroll
        for (int ni = 0; ni < 8; ni++)
#pragma unroll
            for (int j = 0; j < 4; j++) acc[mi][ni][j] = 0.f;

    for (int it = 0; it < 32; ++it) {
        CP_WAIT1();
        __syncthreads();
        const float* st  = sm + (it & 1) * STG_FLOATS;
        const float* pAh = st + AOFF(0);
        const float* pAl = st + AOFF(1);
        const float* pBh = st + BOFF(0);
        const float* pBl = st + BOFF(1);

#pragma unroll
        for (int ks = 0; ks < 2; ks++) {
            const int kb = ks * 8 + fc;
            uint32_t ah[4][4], bh[8][2], bl[8][2];
#pragma unroll
            for (int mi = 0; mi < 4; mi++) {
                const int r = wm * 64 + mi * 16 + fr;
                ah[mi][0] = __float_as_uint(pAh[r * 20 + kb]);
                ah[mi][1] = __float_as_uint(pAh[(r + 8) * 20 + kb]);
                ah[mi][2] = __float_as_uint(pAh[r * 20 + kb + 4]);
                ah[mi][3] = __float_as_uint(pAh[(r + 8) * 20 + kb + 4]);
            }
#pragma unroll
            for (int ni = 0; ni < 8; ni++) {
                const int n = wn * 64 + ni * 8 + fr;
                bh[ni][0] = __float_as_uint(pBh[n * 20 + ks * 8 + fc]);
                bh[ni][1] = __float_as_uint(pBh[n * 20 + ks * 8 + fc + 4]);
                bl[ni][0] = __float_as_uint(pBl[n * 20 + ks * 8 + fc]);
                bl[ni][1] = __float_as_uint(pBl[n * 20 + ks * 8 + fc + 4]);
            }
#pragma unroll
            for (int mi = 0; mi < 4; mi++)
#pragma unroll
                for (int ni = 0; ni < 8; ni++) mma_tf32_16n8k8(acc[mi][ni], ah[mi], bh[ni]);
#pragma unroll
            for (int mi = 0; mi < 4; mi++)
#pragma unroll
                for (int ni = 0; ni < 8; ni++) mma_tf32_16n8k8(acc[mi][ni], ah[mi], bl[ni]);
#pragma unroll
            for (int mi = 0; mi < 4; mi++) {
                const int r = wm * 64 + mi * 16 + fr;
                ah[mi][0] = __float_as_uint(pAl[r * 20 + kb]);
                ah[mi][1] = __float_as_uint(pAl[(r + 8) * 20 + kb]);
                ah[mi][2] = __float_as_uint(pAl[r * 20 + kb + 4]);
                ah[mi][3] = __float_as_uint(pAl[(r + 8) * 20 + kb + 4]);
            }
#pragma unroll
            for (int mi = 0; mi < 4; mi++)
#pragma unroll
                for (int ni = 0; ni < 8; ni++) mma_tf32_16n8k8(acc[mi][ni], ah[mi], bh[ni]);
        }
        __syncthreads();
        if (it + 2 < 32) {
            const uint32_t so = (it & 1) * stgB;
            const int ko = (it + 2) * 16;
            CP_ASYNC(dAhi + so,      gAhi + ko);
            CP_ASYNC(dAhi + so + 16, gAhi + ko + 4);
            CP_ASYNC(dAlo + so,      gAlo + ko);
            CP_ASYNC(dAlo + so + 16, gAlo + ko + 4);
#pragma unroll
            for (int q = 0; q < 4; q++) {
                CP_ASYNC(dBhi + so + q * 16, gBhi + ko + q * 4);
                CP_ASYNC(dBlo + so + q * 16, gBlo + ko + q * 4);
            }
        }
        CP_COMMIT();
    }

    __syncthreads();

    // ---- interval top-2 epilogue ----
    sm[tid] = cbsq[bn + tid];
    u64* s2 = (u64*)(sm + 256);    // [128 rows][4 warps][3]
    __syncthreads();
#pragma unroll
    for (int mi = 0; mi < 4; mi++) {
        const int rl = wm * 64 + mi * 16 + fr;
        const float a0 = Asq[bm + rl], a8 = Asq[bm + rl + 8];
        u64 L1a = ~0ull, H1a = ~0ull, L2a = ~0ull;
        u64 L1b = ~0ull, H1b = ~0ull, L2b = ~0ull;
#pragma unroll
        for (int ni = 0; ni < 8; ni++) {
            const int colL = wn * 64 + ni * 8 + 2 * fc;
            const unsigned col = (unsigned)(bn + colL);
            const float s0 = sm[colL], s1 = sm[colL + 1];
#pragma unroll
            for (int h = 0; h < 2; h++) {
                const float asq = h ? a8 : a0;
                const float d00 = acc[mi][ni][h * 2 + 0];
                const float d01 = acc[mi][ni][h * 2 + 1];
                const float t10 = asq + s0, t11 = asq + s1;
                u64 lo0 = ((u64)__float_as_uint(t10 - 2.0f * (d00 + DELTA)) << 32) | col;
                u64 hi0 = ((u64)__float_as_uint(t10 - 2.0f * (d00 - DELTA)) << 32) | col;
                u64 lo1 = ((u64)__float_as_uint(t11 - 2.0f * (d01 + DELTA)) << 32) | (col + 1);
                u64 hi1 = ((u64)__float_as_uint(t11 - 2.0f * (d01 - DELTA)) << 32) | (col + 1);
                if (h == 0) { top2_push(L1a, H1a, L2a, lo0, hi0); top2_push(L1a, H1a, L2a, lo1, hi1); }
                else        { top2_push(L1b, H1b, L2b, lo0, hi0); top2_push(L1b, H1b, L2b, lo1, hi1); }
            }
        }
#pragma unroll
        for (int o = 1; o <= 2; o <<= 1) {
            u64 l1 = __shfl_xor_sync(0xffffffffu, L1a, o);
            u64 h1 = __shfl_xor_sync(0xffffffffu, H1a, o);
            u64 l2 = __shfl_xor_sync(0xffffffffu, L2a, o);
            top2_mergeT(L1a, H1a, L2a, l1, h1, l2);
            l1 = __shfl_xor_sync(0xffffffffu, L1b, o);
            h1 = __shfl_xor_sync(0xffffffffu, H1b, o);
            l2 = __shfl_xor_sync(0xffffffffu, L2b, o);
            top2_mergeT(L1b, H1b, L2b, l1, h1, l2);
        }
        if (fc == 0) {
            s2[(rl * 4 + wn) * 3]           = L1a;
            s2[(rl * 4 + wn) * 3 + 1]       = H1a;
            s2[(rl * 4 + wn) * 3 + 2]       = L2a;
            s2[((rl + 8) * 4 + wn) * 3]     = L1b;
            s2[((rl + 8) * 4 + wn) * 3 + 1] = H1b;
            s2[((rl + 8) * 4 + wn) * 3 + 2] = L2b;
        }
    }
    __syncthreads();
    if (tid < 128) {
        u64 L1 = s2[(tid * 4) * 3], H1 = s2[(tid * 4) * 3 + 1], L2 = s2[(tid * 4) * 3 + 2];
#pragma unroll
        for (int w = 1; w < 4; w++)
            top2_mergeT(L1, H1, L2, s2[(tid * 4 + w) * 3], s2[(tid * 4 + w) * 3 + 1],
                        s2[(tid * 4 + w) * 3 + 2]);
        const size_t t = (size_t)(bm + tid);
        gtop2[t * 6 + blockIdx.x * 3]     = L1;
        gtop2[t * 6 + blockIdx.x * 3 + 1] = H1;
        gtop2[t * 6 + blockIdx.x * 3 + 2] = L2;
    }
}

// ================= merge chunks, write winner, flag uncertain =================
__global__ void merge_flag(const u64* __restrict__ gtop2, int nch,
                           int* __restrict__ idxout,
                           int* __restrict__ flaglist, int* __restrict__ nflag)
{
    const int t = blockIdx.x * blockDim.x + threadIdx.x;
    if (t >= NTOK) return;
    u64 L1 = gtop2[(size_t)t * 6], H1 = gtop2[(size_t)t * 6 + 1], L2 = gtop2[(size_t)t * 6 + 2];
    if (nch == 2)
        top2_mergeT(L1, H1, L2, gtop2[(size_t)t * 6 + 3], gtop2[(size_t)t * 6 + 4],
                    gtop2[(size_t)t * 6 + 5]);
    idxout[t] = (int)(L1 & 0xFFFFFFFFu);
    if (H1 > L2) {                       // winner not provably FFMA-correct
        const int p = atomicAdd(nflag, 1);
        flaglist[p] = t;
    }
}

// ================= FFMA re-check for flagged tokens (16 tokens/block) =================
#define RT 16
__global__ __launch_bounds__(256)
void refine(const float* __restrict__ feat, const float* __restrict__ cb,
            const float* __restrict__ cbsq, const float* __restrict__ Asq,
            int K, int* __restrict__ idxout,
            const int* __restrict__ flaglist, const int* __restrict__ nflag)
{
    __shared__ float sf[RT * 512];
    __shared__ float sa[RT];
    __shared__ int   stl[RT];
    __shared__ u64   sred[RT][9];
    const int n = *nflag;
    const int tid = threadIdx.x, lane = tid & 31, wid = tid >> 5;
    for (int base = blockIdx.x * RT; base < n; base += gridDim.x * RT) {
        const int nt = min(RT, n - base);
        if (tid < RT) {
            const int t = flaglist[(tid < nt) ? (base + tid) : base];
            stl[tid] = t; sa[tid] = Asq[t];
        }
        __syncthreads();
        for (int i = tid; i < RT * 128; i += 256) {
            const int t = i >> 7, c = i & 127;
            ((float4*)sf)[t * 128 + c] = ((const float4*)(feat + (size_t)stl[t] * 512))[c];
        }
        __syncthreads();
        u64 best[RT];
#pragma unroll
        for (int t = 0; t < RT; t++) best[t] = ~0ull;
        for (int code = tid; code < K; code += 256) {
            float acc[RT];
#pragma unroll
            for (int t = 0; t < RT; t++) acc[t] = 0.f;
            const float4* cp = (const float4*)(cb + (size_t)code * 512);
            for (int k4 = 0; k4 < 128; k4++) {
                const float4 b = __ldg(cp + k4);
#pragma unroll
                for (int t = 0; t < RT; t++) {
                    float a = acc[t];
                    a = fmaf(sf[t * 512 + 4 * k4 + 0], b.x, a);
                    a = fmaf(sf[t * 512 + 4 * k4 + 1], b.y, a);
                    a = fmaf(sf[t * 512 + 4 * k4 + 2], b.z, a);
                    a = fmaf(sf[t * 512 + 4 * k4 + 3], b.w, a);
                    acc[t] = a;
                }
            }
            const float csq = cbsq[code];
#pragma unroll
            for (int t = 0; t < RT; t++) {
                const float d = (sa[t] + csq) - 2.0f * acc[t];
                best[t] = umin64_(best[t], ((u64)__float_as_uint(d) << 32) | (unsigned)code);
            }
        }
#pragma unroll
        for (int t = 0; t < RT; t++) {
            u64 b = best[t];
#pragma unroll
            for (int o = 16; o; o >>= 1) b = umin64_(b, __shfl_xor_sync(0xffffffffu, b, o));
            if (!lane) sred[t][wid] = b;
        }
        __syncthreads();
        if (tid < nt) {
            u64 b = sred[tid][0];
#pragma unroll
            for (int w = 1; w < 8; w++) b = umin64_(b, sred[tid][w]);
            idxout[stl[tid]] = (int)(b & 0xFFFFFFFFu);
        }
        __syncthreads();
    }
}

__global__ void zero_counters() {
    if (threadIdx.x < 4) g_nflag[threadIdx.x] = 0;
}

// ================= convert to tf32 hi/lo + row sumsq (warp per row) =================
__global__ void cvt_hilo_sq(const float* __restrict__ A, float* __restrict__ hi,
                            float* __restrict__ lo, float* __restrict__ sq, int rows)
{
    const int row = blockIdx.x * (blockDim.x >> 5) + (threadIdx.x >> 5);
    if (row >= rows) return;
    const int lane = threadIdx.x & 31;
    const float4* p = (const float4*)(A + (size_t)row * 512);
    float4* ph = (float4*)(hi + (size_t)row * 512);
    float4* pl = (float4*)(lo + (size_t)row * 512);
    float s = 0.f;
#pragma unroll
    for (int i = 0; i < 4; i++) {
        float4 v = p[lane + 32 * i];
        s += v.x * v.x; s += v.y * v.y; s += v.z * v.z; s += v.w * v.w;
        float4 h, l;
        h.x = to_tf32(v.x); l.x = to_tf32(v.x - h.x);
        h.y = to_tf32(v.y); l.y = to_tf32(v.y - h.y);
        h.z = to_tf32(v.z); l.z = to_tf32(v.z - h.z);
        h.w = to_tf32(v.w); l.w = to_tf32(v.w - h.w);
        ph[lane + 32 * i] = h; pl[lane + 32 * i] = l;
    }
#pragma unroll
    for (int o = 16; o; o >>= 1) s += __shfl_xor_sync(0xffffffffu, s, o);
    if (!lane) sq[row] = s;
}

// ================= residual = df - cb0[idx0] =================
__global__ void residual_idx(const float* __restrict__ df, const float* __restrict__ cb0,
                             const int* __restrict__ idx, float* __restrict__ res)
{
    const int row = blockIdx.x, t = threadIdx.x;
    const int id = idx[row];
    float4 v = ((const float4*)(df  + (size_t)row * 512))[t];
    float4 q = ((const float4*)(cb0 + (size_t)id  * 512))[t];
    ((float4*)(res + (size_t)row * 512))[t] =
        make_float4(v.x - q.x, v.y - q.y, v.z - q.z, v.w - q.w);
}

// ================= FFMA GEMM (features + P projections; R1-validated rounding class) =================
__global__ __launch_bounds__(256)
void gemm_nt(const float* __restrict__ A, int lda,
             const float* __restrict__ W, int ldw,
             const float* __restrict__ bias,
             float* __restrict__ C, int ldc, int Kin)
{
    __shared__ alignas(16) float sA[2][16][68];
    __shared__ alignas(16) float sB[2][16][132];
    const int tid = threadIdx.x;
    const int bm = blockIdx.y * 64;
    const int bn = blockIdx.x * 128;
    const int tx = tid & 15, ty = tid >> 4;
    const int arow = tid >> 2, akq = (tid & 3) << 2;
    const int bcol0 = arow, bcol1 = arow + 64;
    const float* Ap  = A + (size_t)(bm + arow) * lda + akq;
    const float* Wp0 = W + (size_t)(bn + bcol0) * ldw + akq;
    const float* Wp1 = W + (size_t)(bn + bcol1) * ldw + akq;
    float4 pa = *(const float4*)Ap, pb0 = *(const float4*)Wp0, pb1 = *(const float4*)Wp1;
    sA[0][akq + 0][arow] = pa.x;  sA[0][akq + 1][arow] = pa.y;
    sA[0][akq + 2][arow] = pa.z;  sA[0][akq + 3][arow] = pa.w;
    sB[0][akq + 0][bcol0] = pb0.x; sB[0][akq + 1][bcol0] = pb0.y;
    sB[0][akq + 2][bcol0] = pb0.z; sB[0][akq + 3][bcol0] = pb0.w;
    sB[0][akq + 0][bcol1] = pb1.x; sB[0][akq + 1][bcol1] = pb1.y;
    sB[0][akq + 2][bcol1] = pb1.z; sB[0][akq + 3][bcol1] = pb1.w;
    __syncthreads();
    float acc[4][8];
#pragma unroll
    for (int i = 0; i < 4; i++)
#pragma unroll
        for (int j = 0; j < 8; j++) acc[i][j] = 0.f;
    const int nk = Kin >> 4;
    for (int t = 0; t < nk; ++t) {
        const int cur = t & 1;
        if (t + 1 < nk) {
            pa  = *(const float4*)(Ap  + (t + 1) * 16);
            pb0 = *(const float4*)(Wp0 + (t + 1) * 16);
            pb1 = *(const float4*)(Wp1 + (t + 1) * 16);
        }
#pragma unroll
        for (int kk = 0; kk < 16; ++kk) {
            float4 fa  = *(const float4*)&sA[cur][kk][ty << 2];
            float4 fb0 = *(const float4*)&sB[cur][kk][tx << 3];
            float4 fb1 = *(const float4*)&sB[cur][kk][(tx << 3) + 4];
            float av[4] = {fa.x, fa.y, fa.z, fa.w};
            float bv[8] = {fb0.x, fb0.y, fb0.z, fb0.w, fb1.x, fb1.y, fb1.z, fb1.w};
#pragma unroll
            for (int i = 0; i < 4; i++)
#pragma unroll
                for (int j = 0; j < 8; j++) acc[i][j] += av[i] * bv[j];
        }
        if (t + 1 < nk) {
            const int nxt = cur ^ 1;
            sA[nxt][akq + 0][arow] = pa.x;  sA[nxt][akq + 1][arow] = pa.y;
            sA[nxt][akq + 2][arow] = pa.z;  sA[nxt][akq + 3][arow] = pa.w;
            sB[nxt][akq + 0][bcol0] = pb0.x; sB[nxt][akq + 1][bcol0] = pb0.y;
            sB[nxt][akq + 2][bcol0] = pb0.z; sB[nxt][akq + 3][bcol0] = pb0.w;
            sB[nxt][akq + 0][bcol1] = pb1.x; sB[nxt][akq + 1][bcol1] = pb1.y;
            sB[nxt][akq + 2][bcol1] = pb1.z; sB[nxt][akq + 3][bcol1] = pb1.w;
        }
        __syncthreads();
    }
#pragma unroll
    for (int i = 0; i < 4; i++) {
        const int m = bm + (ty << 2) + i;
        float* Cr = C + (size_t)m * ldc + bn + (tx << 3);
#pragma unroll
        for (int j = 0; j < 8; j++) {
            float v = acc[i][j];
            if (bias) v += bias[bn + (tx << 3) + j];
            Cr[j] = v;
        }
    }
}

// ================= losses =================
__global__ __launch_bounds__(256)
void loss_kernel(const float* __restrict__ tcb, const float* __restrict__ ecb,
                 const float* __restrict__ cb0, const float* __restrict__ cb1)
{
    double s = 0.0;
    const int total = NTOK * 128;
    for (int i = blockIdx.x * 256 + threadIdx.x; i < total; i += 4096 * 256) {
        const int row = i >> 7, c = i & 127;
        float ps = 0.f;
        {
            float4 q = ((const float4*)(tcb + (size_t)g_idx[row] * 512))[c];
            float4 a = ((const float4*)(g_tf + (size_t)row * 512))[c];
            float dx = q.x - a.x, dy = q.y - a.y, dz = q.z - a.z, dw = q.w - a.w;
            ps += dx * dx + dy * dy + dz * dz + dw * dw;
        }
        {
            float4 q = ((const float4*)(ecb + (size_t)g_idx[NTOK + row] * 512))[c];
            float4 a = ((const float4*)(g_ef + (size_t)row * 512))[c];
            float dx = q.x - a.x, dy = q.y - a.y, dz = q.z - a.z, dw = q.w - a.w;
            ps += dx * dx + dy * dy + dz * dz + dw * dw;
        }
        {
            float4 q = ((const float4*)(cb0 + (size_t)g_idx[2 * NTOK + row] * 512))[c];
            float4 a = ((const float4*)(g_df + (size_t)row * 512))[c];
            float dx = q.x - a.x, dy = q.y - a.y, dz = q.z - a.z, dw = q.w - a.w;
            ps += dx * dx + dy * dy + dz * dz + dw * dw;
        }
        {
            float4 q = ((const float4*)(cb1 + (size_t)g_idx[3 * NTOK + row] * 512))[c];
            float4 a = ((const float4*)(g_res + (size_t)row * 512))[c];
            float dx = q.x - a.x, dy = q.y - a.y, dz = q.z - a.z, dw = q.w - a.w;
            ps += dx * dx + dy * dy + dz * dz + dw * dw;
        }
        s += (double)ps;
    }
    __shared__ double sh[256];
    sh[threadIdx.x] = s; __syncthreads();
    for (int o = 128; o; o >>= 1) {
        if (threadIdx.x < o) sh[threadIdx.x] += sh[threadIdx.x + o];
        __syncthreads();
    }
    if (!threadIdx.x) g_losspart[blockIdx.x] = sh[0];
}

__global__ void loss_final(float* __restrict__ out)
{
    __shared__ double sh[256];
    double s = 0.0;
    for (int i = threadIdx.x; i < 4096; i += 256) s += g_losspart[i];
    sh[threadIdx.x] = s; __syncthreads();
    for (int o = 128; o; o >>= 1) {
        if (threadIdx.x < o) sh[threadIdx.x] += sh[threadIdx.x + o];
        __syncthreads();
    }
    if (!threadIdx.x) out[0] = (float)(1.25 * sh[0] / (double)NQ);
}

// ================= output gather + idx =================
__global__ void out_gather(const float* __restrict__ outb, float* __restrict__ out)
{
    const int row = blockIdx.x, t = threadIdx.x;
    const int it = g_idx[row];
    const int ie = g_idx[NTOK + row];
    const int i0 = g_idx[2 * NTOK + row];
    const int i1 = g_idx[3 * NTOK + row];
    float4 b  = ((const float4*)outb)[t];
    float4 a0 = ((const float4*)(g_P + (size_t)it * 512))[t];
    float4 a1 = ((const float4*)(g_P + (size_t)(512  + ie) * 512))[t];
    float4 a2 = ((const float4*)(g_P + (size_t)(768  + i0) * 512))[t];
    float4 a3 = ((const float4*)(g_P + (size_t)(1280 + i1) * 512))[t];
    ((float4*)(out + (size_t)row * 512))[t] =
        make_float4(b.x + a0.x + a1.x + a2.x + a3.x,
                    b.y + a0.y + a1.y + a2.y + a3.y,
                    b.z + a0.z + a1.z + a2.z + a3.z,
                    b.w + a0.w + a1.w + a2.w + a3.w);
}

__global__ void write_idx(float* __restrict__ out)
{
    const int i = blockIdx.x * 256 + threadIdx.x;
    if (i < NTOK) {
        out[NQ + i]            = (float)g_idx[i];
        out[NQ + NTOK + i]     = (float)g_idx[NTOK + i];
        out[NQ + 2 * NTOK + i] = (float)g_idx[2 * NTOK + i];
        out[NQ + 3 * NTOK + i] = (float)g_idx[3 * NTOK + i];
    }
}

// =====================================================================
extern "C" void kernel_launch(void* const* d_in, const int* in_sizes, int n_in,
                              void* d_out, int out_size)
{
    const float* x   = (const float*)d_in[0];
    const float* tW  = (const float*)d_in[1];
    const float* tb  = (const float*)d_in[2];
    const float* eW  = (const float*)d_in[3];
    const float* eb  = (const float*)d_in[4];
    const float* dW  = (const float*)d_in[5];
    const float* db  = (const float*)d_in[6];
    const float* oW  = (const float*)d_in[7];
    const float* ob  = (const float*)d_in[8];
    const float* tcb = (const float*)d_in[9];
    const float* ecb = (const float*)d_in[10];
    const float* cb0 = (const float*)d_in[11];
    const float* cb1 = (const float*)d_in[12];
    float* out = (float*)d_out;

    void* p;
    cudaGetSymbolAddress(&p, g_tf);    float* tf    = (float*)p;
    cudaGetSymbolAddress(&p, g_ef);    float* ef    = (float*)p;
    cudaGetSymbolAddress(&p, g_df);    float* df    = (float*)p;
    cudaGetSymbolAddress(&p, g_res);   float* res   = (float*)p;
    cudaGetSymbolAddress(&p, g_fhi);   float* fhi   = (float*)p;
    cudaGetSymbolAddress(&p, g_flo);   float* flo   = (float*)p;
    cudaGetSymbolAddress(&p, g_reshi); float* reshi = (float*)p;
    cudaGetSymbolAddress(&p, g_reslo); float* reslo = (float*)p;
    cudaGetSymbolAddress(&p, g_cbhi);  float* cbhi  = (float*)p;
    cudaGetSymbolAddress(&p, g_cblo);  float* cblo  = (float*)p;
    cudaGetSymbolAddress(&p, g_sqA);   float* sqA   = (float*)p;
    cudaGetSymbolAddress(&p, g_cbsq);  float* cbsq  = (float*)p;
    cudaGetSymbolAddress(&p, g_idx);   int*   idx   = (int*)p;
    cudaGetSymbolAddress(&p, g_top2);  u64*   top2  = (u64*)p;
    cudaGetSymbolAddress(&p, g_nflag); int*   nfl   = (int*)p;
    cudaGetSymbolAddress(&p, g_flagged); int* flg   = (int*)p;
    cudaGetSymbolAddress(&p, g_P);     float* P     = (float*)p;

    cudaFuncSetAttribute(vq3t, cudaFuncAttributeMaxDynamicSharedMemorySize, GEMM_SMEM);

    // 1) codebook hi/lo decompositions + sumsq
    cvt_hilo_sq<<<64, 256>>>(tcb, cbhi,              cblo,              cbsq,        512);
    cvt_hilo_sq<<<32, 256>>>(ecb, cbhi + 512 * 512,  cblo + 512 * 512,  cbsq + 512,  256);
    cvt_hilo_sq<<<64, 256>>>(cb0, cbhi + 768 * 512,  cblo + 768 * 512,  cbsq + 768,  512);
    cvt_hilo_sq<<<64, 256>>>(cb1, cbhi + 1280 * 512, cblo + 1280 * 512, cbsq + 1280, 512);

    // 2) feature linears — R1-validated fp32 FFMA GEMM (reference-matching class;
    //    REQUIRED: the refine's boundary decisions are only validated on these features)
    dim3 gFeat(4, 1024);
    gemm_nt<<<gFeat, 256>>>(x, 512, tW, 512, tb, tf, 512, 512);
    gemm_nt<<<gFeat, 256>>>(x, 512, eW, 512, eb, ef, 512, 512);
    gemm_nt<<<gFeat, 256>>>(x, 512, dW, 512, db, df, 512, 512);

    // 3) feature hi/lo + row sumsq
    cvt_hilo_sq<<<8192, 256>>>(tf, fhi,          flo,          sqA,            NTOK);
    cvt_hilo_sq<<<8192, 256>>>(ef, fhi + NQ,     flo + NQ,     sqA + NTOK,     NTOK);
    cvt_hilo_sq<<<8192, 256>>>(df, fhi + 2 * NQ, flo + 2 * NQ, sqA + 2 * NTOK, NTOK);

    zero_counters<<<1, 32>>>();

    // 4) timbre: tensor VQ -> merge/flag (interval test) -> FFMA refine
    vq3t<<<dim3(2, 512), 256, GEMM_SMEM>>>(fhi, flo, cbhi, cblo, sqA, cbsq, top2);
    merge_flag<<<256, 256>>>(top2, 2, idx, flg, nfl);
    refine<<<512, 256>>>(tf, tcb, cbsq, sqA, 512, idx, flg, nfl);

    // 5) expr
    vq3t<<<dim3(1, 512), 256, GEMM_SMEM>>>(fhi + NQ, flo + NQ,
                                           cbhi + 512 * 512, cblo + 512 * 512,
                                           sqA + NTOK, cbsq + 512, top2);
    merge_flag<<<256, 256>>>(top2, 1, idx + NTOK, flg + NTOK, nfl + 1);
    refine<<<512, 256>>>(ef, ecb, cbsq + 512, sqA + NTOK, 256, idx + NTOK, flg + NTOK, nfl + 1);

    // 6) detail stage 0
    vq3t<<<dim3(2, 512), 256, GEMM_SMEM>>>(fhi + 2 * NQ, flo + 2 * NQ,
                                           cbhi + 768 * 512, cblo + 768 * 512,
                                           sqA + 2 * NTOK, cbsq + 768, top2);
    merge_flag<<<256, 256>>>(top2, 2, idx + 2 * NTOK, flg + 2 * NTOK, nfl + 2);
    refine<<<512, 256>>>(df, cb0, cbsq + 768, sqA + 2 * NTOK, 512, idx + 2 * NTOK,
                         flg + 2 * NTOK, nfl + 2);

    // 7) residual + detail stage 1
    residual_idx<<<NTOK, 128>>>(df, cb0, idx + 2 * NTOK, res);
    cvt_hilo_sq<<<8192, 256>>>(res, reshi, reslo, sqA + 3 * NTOK, NTOK);
    vq3t<<<dim3(2, 512), 256, GEMM_SMEM>>>(reshi, reslo,
                                           cbhi + 1280 * 512, cblo + 1280 * 512,
                                           sqA + 3 * NTOK, cbsq + 1280, top2);
    merge_flag<<<256, 256>>>(top2, 2, idx + 3 * NTOK, flg + 3 * NTOK, nfl + 3);
    refine<<<512, 256>>>(res, cb1, cbsq + 1280, sqA + 3 * NTOK, 512, idx + 3 * NTOK,
                         flg + 3 * NTOK, nfl + 3);

    // 8) loss
    loss_kernel<<<4096, 256>>>(tcb, ecb, cb0, cb1);
    loss_final<<<1, 256>>>(out + NQ + 4 * NTOK);

    // 9) projected codebooks (small FFMA GEMMs)
    gemm_nt<<<dim3(4, 8), 256>>>(tcb, 512, oW,        1536, nullptr, P,              512, 512);
    gemm_nt<<<dim3(4, 4), 256>>>(ecb, 512, oW + 512,  1536, nullptr, P + 512  * 512, 512, 512);
    gemm_nt<<<dim3(4, 8), 256>>>(cb0, 512, oW + 1024, 1536, nullptr, P + 768  * 512, 512, 512);
    gemm_nt<<<dim3(4, 8), 256>>>(cb1, 512, oW + 1024, 1536, nullptr, P + 1280 * 512, 512, 512);

    // 10) outputs
    out_gather<<<NTOK, 128>>>(ob, out);
    write_idx<<<256, 256>>>(out);
}

// round 15
// speedup vs baseline: 1.2302x; 1.2302x over previous
#include <cuda_runtime.h>
#include <stdint.h>

#define NTOK 65536
#define DIM  512
#define NQ   (NTOK * DIM)
#define DELTA 2e-6f

typedef unsigned long long u64;

// ====================== scratch (device globals) ======================
__device__ float g_tf[NQ];
__device__ float g_ef[NQ];
__device__ float g_df[NQ];
__device__ float g_res[NQ];
__device__ float g_fhi[3 * NQ], g_flo[3 * NQ];        // tf, ef, df hi/lo
__device__ float g_reshi[NQ], g_reslo[NQ];
__device__ float g_cbhi[1792 * 512], g_cblo[1792 * 512];  // tcb@0, ecb@512, cb0@768, cb1@1280
__device__ float g_sqA[4 * NTOK];
__device__ float g_cbsq[1792];
__device__ int   g_idx[4 * NTOK];
__device__ u64   g_top2[NTOK * 6];                 // per token: 2 chunks x (L1,H1,L2)
__device__ int   g_nflag[4];
__device__ int   g_flagged[4][NTOK];
__device__ float g_P[1792 * DIM];
__device__ double g_losspart[4096];

// ====================== helpers ======================
__device__ __forceinline__ uint32_t smem_to_u32(const void* p) {
    uint32_t a;
    asm("{ .reg .u64 t; cvta.to.shared.u64 t, %1; cvt.u32.u64 %0, t; }" : "=r"(a) : "l"(p));
    return a;
}
__device__ __forceinline__ float to_tf32(float f) {
    float r;
    asm("cvt.rna.tf32.f32 %0, %1;" : "=f"(r) : "f"(f));
    return r;
}
#define CP_ASYNC(dst, src) \
    asm volatile("cp.async.cg.shared.global [%0], [%1], 16;" :: "r"(dst), "l"(src) : "memory")
#define CP_COMMIT() asm volatile("cp.async.commit_group;" ::: "memory")
#define CP_WAIT1()  asm volatile("cp.async.wait_group 1;" ::: "memory")

__device__ __forceinline__ void mma_tf32_16n8k8(float c[4], const uint32_t a[4], const uint32_t b[2]) {
    asm volatile("mma.sync.aligned.m16n8k8.row.col.f32.tf32.tf32.f32 "
                 "{%0,%1,%2,%3}, {%4,%5,%6,%7}, {%8,%9}, {%0,%1,%2,%3};"
                 : "+f"(c[0]), "+f"(c[1]), "+f"(c[2]), "+f"(c[3])
                 : "r"(a[0]), "r"(a[1]), "r"(a[2]), "r"(a[3]), "r"(b[0]), "r"(b[1]));
}

__device__ __forceinline__ u64 umin64_(u64 a, u64 b) { return a < b ? a : b; }

// push candidate (L,H) into (L1,H1,L2) [top-2 by L, H carried with winner]
__device__ __forceinline__ void top2_push(u64& L1, u64& H1, u64& L2, u64 L, u64 H) {
    if (L < L1) { L2 = L1; L1 = L; H1 = H; } else if (L < L2) { L2 = L; }
}
// merge another triple in
__device__ __forceinline__ void top2_mergeT(u64& L1, u64& H1, u64& L2, u64 l1, u64 h1, u64 l2) {
    if (l1 < L1) { L2 = umin64_(L1, l2); L1 = l1; H1 = h1; }
    else         { L2 = umin64_(l1, L2); }
}

// ====================== VQ distance GEMM, 3xTF32 split (mma.sync) ======================
// BM=128, BN=256, BK=16. 8 warps (2m x 4n), warp tile 64x64.
// Interval top-2 epilogue: dlo/dhi = fl(fl(Asq+cbsq) - 2(dot +/- DELTA));
// per-token (L1,H1,L2) -> gtop2[token*6 + chunk*3 ...].
#define STG_FLOATS 15360
#define AOFF(arr)  ((arr) * 2560)
#define BOFF(arr)  (5120 + (arr) * 5120)
#define GEMM_SMEM  (2 * STG_FLOATS * 4)       // 122880 bytes

__global__ __launch_bounds__(256, 1)
void vq3t(const float* __restrict__ Ahi, const float* __restrict__ Alo,
          const float* __restrict__ Bhi, const float* __restrict__ Blo,
          const float* __restrict__ Asq, const float* __restrict__ cbsq,
          u64* __restrict__ gtop2)
{
    extern __shared__ float sm[];
    const uint32_t smu = smem_to_u32(sm);
    const int tid  = threadIdx.x;
    const int lane = tid & 31, wid = tid >> 5;
    const int wm = wid >> 2, wn = wid & 3;
    const int bm = blockIdx.y * 128, bn = blockIdx.x * 256;
    const int fr = lane >> 2, fc = lane & 3;

    const int aRow = tid >> 1, aQ = (tid & 1) * 2;
    const int bRow = tid;
    const float* gAhi = Ahi + (size_t)(bm + aRow) * 512 + aQ * 4;
    const float* gAlo = Alo + (size_t)(bm + aRow) * 512 + aQ * 4;
    const float* gBhi = Bhi + (size_t)(bn + bRow) * 512;
    const float* gBlo = Blo + (size_t)(bn + bRow) * 512;
    const uint32_t dAhi = smu + (uint32_t)(AOFF(0) + aRow * 20 + aQ * 4) * 4u;
    const uint32_t dAlo = smu + (uint32_t)(AOFF(1) + aRow * 20 + aQ * 4) * 4u;
    const uint32_t dBhi = smu + (uint32_t)(BOFF(0) + bRow * 20) * 4u;
    const uint32_t dBlo = smu + (uint32_t)(BOFF(1) + bRow * 20) * 4u;
    const uint32_t stgB = STG_FLOATS * 4u;

#pragma unroll
    for (int s = 0; s < 2; s++) {
        const uint32_t so = s * stgB;
        const int ko = s * 16;
        CP_ASYNC(dAhi + so,      gAhi + ko);
        CP_ASYNC(dAhi + so + 16, gAhi + ko + 4);
        CP_ASYNC(dAlo + so,      gAlo + ko);
        CP_ASYNC(dAlo + so + 16, gAlo + ko + 4);
#pragma unroll
        for (int q = 0; q < 4; q++) {
            CP_ASYNC(dBhi + so + q * 16, gBhi + ko + q * 4);
            CP_ASYNC(dBlo + so + q * 16, gBlo + ko + q * 4);
        }
        CP_COMMIT();
    }

    float acc[4][8][4];
#pragma unroll
    for (int mi = 0; mi < 4; mi++)
#pragma unroll
        for (int ni = 0; ni < 8; ni++)
#pragma unroll
            for (int j = 0; j < 4; j++) acc[mi][ni][j] = 0.f;

    for (int it = 0; it < 32; ++it) {
        CP_WAIT1();
        __syncthreads();
        const float* st  = sm + (it & 1) * STG_FLOATS;
        const float* pAh = st + AOFF(0);
        const float* pAl = st + AOFF(1);
        const float* pBh = st + BOFF(0);
        const float* pBl = st + BOFF(1);

#pragma unroll
        for (int ks = 0; ks < 2; ks++) {
            const int kb = ks * 8 + fc;
            uint32_t ah[4][4], bh[8][2], bl[8][2];
#pragma unroll
            for (int mi = 0; mi < 4; mi++) {
                const int r = wm * 64 + mi * 16 + fr;
                ah[mi][0] = __float_as_uint(pAh[r * 20 + kb]);
                ah[mi][1] = __float_as_uint(pAh[(r + 8) * 20 + kb]);
                ah[mi][2] = __float_as_uint(pAh[r * 20 + kb + 4]);
                ah[mi][3] = __float_as_uint(pAh[(r + 8) * 20 + kb + 4]);
            }
#pragma unroll
            for (int ni = 0; ni < 8; ni++) {
                const int n = wn * 64 + ni * 8 + fr;
                bh[ni][0] = __float_as_uint(pBh[n * 20 + ks * 8 + fc]);
                bh[ni][1] = __float_as_uint(pBh[n * 20 + ks * 8 + fc + 4]);
                bl[ni][0] = __float_as_uint(pBl[n * 20 + ks * 8 + fc]);
                bl[ni][1] = __float_as_uint(pBl[n * 20 + ks * 8 + fc + 4]);
            }
#pragma unroll
            for (int mi = 0; mi < 4; mi++)
#pragma unroll
                for (int ni = 0; ni < 8; ni++) mma_tf32_16n8k8(acc[mi][ni], ah[mi], bh[ni]);
#pragma unroll
            for (int mi = 0; mi < 4; mi++)
#pragma unroll
                for (int ni = 0; ni < 8; ni++) mma_tf32_16n8k8(acc[mi][ni], ah[mi], bl[ni]);
#pragma unroll
            for (int mi = 0; mi < 4; mi++) {
                const int r = wm * 64 + mi * 16 + fr;
                ah[mi][0] = __float_as_uint(pAl[r * 20 + kb]);
                ah[mi][1] = __float_as_uint(pAl[(r + 8) * 20 + kb]);
                ah[mi][2] = __float_as_uint(pAl[r * 20 + kb + 4]);
                ah[mi][3] = __float_as_uint(pAl[(r + 8) * 20 + kb + 4]);
            }
#pragma unroll
            for (int mi = 0; mi < 4; mi++)
#pragma unroll
                for (int ni = 0; ni < 8; ni++) mma_tf32_16n8k8(acc[mi][ni], ah[mi], bh[ni]);
        }
        __syncthreads();
        if (it + 2 < 32) {
            const uint32_t so = (it & 1) * stgB;
            const int ko = (it + 2) * 16;
            CP_ASYNC(dAhi + so,      gAhi + ko);
            CP_ASYNC(dAhi + so + 16, gAhi + ko + 4);
            CP_ASYNC(dAlo + so,      gAlo + ko);
            CP_ASYNC(dAlo + so + 16, gAlo + ko + 4);
#pragma unroll
            for (int q = 0; q < 4; q++) {
                CP_ASYNC(dBhi + so + q * 16, gBhi + ko + q * 4);
                CP_ASYNC(dBlo + so + q * 16, gBlo + ko + q * 4);
            }
        }
        CP_COMMIT();
    }

    __syncthreads();

    // ---- interval top-2 epilogue ----
    sm[tid] = cbsq[bn + tid];
    u64* s2 = (u64*)(sm + 256);    // [128 rows][4 warps][3]
    __syncthreads();
#pragma unroll
    for (int mi = 0; mi < 4; mi++) {
        const int rl = wm * 64 + mi * 16 + fr;
        const float a0 = Asq[bm + rl], a8 = Asq[bm + rl + 8];
        u64 L1a = ~0ull, H1a = ~0ull, L2a = ~0ull;
        u64 L1b = ~0ull, H1b = ~0ull, L2b = ~0ull;
#pragma unroll
        for (int ni = 0; ni < 8; ni++) {
            const int colL = wn * 64 + ni * 8 + 2 * fc;
            const unsigned col = (unsigned)(bn + colL);
            const float s0 = sm[colL], s1 = sm[colL + 1];
#pragma unroll
            for (int h = 0; h < 2; h++) {
                const float asq = h ? a8 : a0;
                const float d00 = acc[mi][ni][h * 2 + 0];
                const float d01 = acc[mi][ni][h * 2 + 1];
                const float t10 = asq + s0, t11 = asq + s1;
                u64 lo0 = ((u64)__float_as_uint(t10 - 2.0f * (d00 + DELTA)) << 32) | col;
                u64 hi0 = ((u64)__float_as_uint(t10 - 2.0f * (d00 - DELTA)) << 32) | col;
                u64 lo1 = ((u64)__float_as_uint(t11 - 2.0f * (d01 + DELTA)) << 32) | (col + 1);
                u64 hi1 = ((u64)__float_as_uint(t11 - 2.0f * (d01 - DELTA)) << 32) | (col + 1);
                if (h == 0) { top2_push(L1a, H1a, L2a, lo0, hi0); top2_push(L1a, H1a, L2a, lo1, hi1); }
                else        { top2_push(L1b, H1b, L2b, lo0, hi0); top2_push(L1b, H1b, L2b, lo1, hi1); }
            }
        }
#pragma unroll
        for (int o = 1; o <= 2; o <<= 1) {
            u64 l1 = __shfl_xor_sync(0xffffffffu, L1a, o);
            u64 h1 = __shfl_xor_sync(0xffffffffu, H1a, o);
            u64 l2 = __shfl_xor_sync(0xffffffffu, L2a, o);
            top2_mergeT(L1a, H1a, L2a, l1, h1, l2);
            l1 = __shfl_xor_sync(0xffffffffu, L1b, o);
            h1 = __shfl_xor_sync(0xffffffffu, H1b, o);
            l2 = __shfl_xor_sync(0xffffffffu, L2b, o);
            top2_mergeT(L1b, H1b, L2b, l1, h1, l2);
        }
        if (fc == 0) {
            s2[(rl * 4 + wn) * 3]           = L1a;
            s2[(rl * 4 + wn) * 3 + 1]       = H1a;
            s2[(rl * 4 + wn) * 3 + 2]       = L2a;
            s2[((rl + 8) * 4 + wn) * 3]     = L1b;
            s2[((rl + 8) * 4 + wn) * 3 + 1] = H1b;
            s2[((rl + 8) * 4 + wn) * 3 + 2] = L2b;
        }
    }
    __syncthreads();
    if (tid < 128) {
        u64 L1 = s2[(tid * 4) * 3], H1 = s2[(tid * 4) * 3 + 1], L2 = s2[(tid * 4) * 3 + 2];
#pragma unroll
        for (int w = 1; w < 4; w++)
            top2_mergeT(L1, H1, L2, s2[(tid * 4 + w) * 3], s2[(tid * 4 + w) * 3 + 1],
                        s2[(tid * 4 + w) * 3 + 2]);
        const size_t t = (size_t)(bm + tid);
        gtop2[t * 6 + blockIdx.x * 3]     = L1;
        gtop2[t * 6 + blockIdx.x * 3 + 1] = H1;
        gtop2[t * 6 + blockIdx.x * 3 + 2] = L2;
    }
}

// ================= merge chunks, write winner, flag uncertain =================
__global__ void merge_flag(const u64* __restrict__ gtop2, int nch,
                           int* __restrict__ idxout,
                           int* __restrict__ flaglist, int* __restrict__ nflag)
{
    const int t = blockIdx.x * blockDim.x + threadIdx.x;
    if (t >= NTOK) return;
    u64 L1 = gtop2[(size_t)t * 6], H1 = gtop2[(size_t)t * 6 + 1], L2 = gtop2[(size_t)t * 6 + 2];
    if (nch == 2)
        top2_mergeT(L1, H1, L2, gtop2[(size_t)t * 6 + 3], gtop2[(size_t)t * 6 + 4],
                    gtop2[(size_t)t * 6 + 5]);
    idxout[t] = (int)(L1 & 0xFFFFFFFFu);
    if (H1 > L2) {                       // winner not provably FFMA-correct
        const int p = atomicAdd(nflag, 1);
        flaglist[p] = t;
    }
}

// ================= FFMA re-check for flagged tokens (16 tokens/block) =================
#define RT 16
__global__ __launch_bounds__(256)
void refine(const float* __restrict__ feat, const float* __restrict__ cb,
            const float* __restrict__ cbsq, const float* __restrict__ Asq,
            int K, int* __restrict__ idxout,
            const int* __restrict__ flaglist, const int* __restrict__ nflag)
{
    __shared__ float sf[RT * 512];
    __shared__ float sa[RT];
    __shared__ int   stl[RT];
    __shared__ u64   sred[RT][9];
    const int n = *nflag;
    const int tid = threadIdx.x, lane = tid & 31, wid = tid >> 5;
    for (int base = blockIdx.x * RT; base < n; base += gridDim.x * RT) {
        const int nt = min(RT, n - base);
        if (tid < RT) {
            const int t = flaglist[(tid < nt) ? (base + tid) : base];
            stl[tid] = t; sa[tid] = Asq[t];
        }
        __syncthreads();
        for (int i = tid; i < RT * 128; i += 256) {
            const int t = i >> 7, c = i & 127;
            ((float4*)sf)[t * 128 + c] = ((const float4*)(feat + (size_t)stl[t] * 512))[c];
        }
        __syncthreads();
        u64 best[RT];
#pragma unroll
        for (int t = 0; t < RT; t++) best[t] = ~0ull;
        for (int code = tid; code < K; code += 256) {
            float acc[RT];
#pragma unroll
            for (int t = 0; t < RT; t++) acc[t] = 0.f;
            const float4* cp = (const float4*)(cb + (size_t)code * 512);
            for (int k4 = 0; k4 < 128; k4++) {
                const float4 b = __ldg(cp + k4);
#pragma unroll
                for (int t = 0; t < RT; t++) {
                    float a = acc[t];
                    a = fmaf(sf[t * 512 + 4 * k4 + 0], b.x, a);
                    a = fmaf(sf[t * 512 + 4 * k4 + 1], b.y, a);
                    a = fmaf(sf[t * 512 + 4 * k4 + 2], b.z, a);
                    a = fmaf(sf[t * 512 + 4 * k4 + 3], b.w, a);
                    acc[t] = a;
                }
            }
            const float csq = cbsq[code];
#pragma unroll
            for (int t = 0; t < RT; t++) {
                const float d = (sa[t] + csq) - 2.0f * acc[t];
                best[t] = umin64_(best[t], ((u64)__float_as_uint(d) << 32) | (unsigned)code);
            }
        }
#pragma unroll
        for (int t = 0; t < RT; t++) {
            u64 b = best[t];
#pragma unroll
            for (int o = 16; o; o >>= 1) b = umin64_(b, __shfl_xor_sync(0xffffffffu, b, o));
            if (!lane) sred[t][wid] = b;
        }
        __syncthreads();
        if (tid < nt) {
            u64 b = sred[tid][0];
#pragma unroll
            for (int w = 1; w < 8; w++) b = umin64_(b, sred[tid][w]);
            idxout[stl[tid]] = (int)(b & 0xFFFFFFFFu);
        }
        __syncthreads();
    }
}

__global__ void zero_counters() {
    if (threadIdx.x < 4) g_nflag[threadIdx.x] = 0;
}

// ================= convert to tf32 hi/lo + row sumsq (warp per row) =================
__global__ void cvt_hilo_sq(const float* __restrict__ A, float* __restrict__ hi,
                            float* __restrict__ lo, float* __restrict__ sq, int rows)
{
    const int row = blockIdx.x * (blockDim.x >> 5) + (threadIdx.x >> 5);
    if (row >= rows) return;
    const int lane = threadIdx.x & 31;
    const float4* p = (const float4*)(A + (size_t)row * 512);
    float4* ph = (float4*)(hi + (size_t)row * 512);
    float4* pl = (float4*)(lo + (size_t)row * 512);
    float s = 0.f;
#pragma unroll
    for (int i = 0; i < 4; i++) {
        float4 v = p[lane + 32 * i];
        s += v.x * v.x; s += v.y * v.y; s += v.z * v.z; s += v.w * v.w;
        float4 h, l;
        h.x = to_tf32(v.x); l.x = to_tf32(v.x - h.x);
        h.y = to_tf32(v.y); l.y = to_tf32(v.y - h.y);
        h.z = to_tf32(v.z); l.z = to_tf32(v.z - h.z);
        h.w = to_tf32(v.w); l.w = to_tf32(v.w - h.w);
        ph[lane + 32 * i] = h; pl[lane + 32 * i] = l;
    }
#pragma unroll
    for (int o = 16; o; o >>= 1) s += __shfl_xor_sync(0xffffffffu, s, o);
    if (!lane) sq[row] = s;
}

// ================= residual = df - cb0[idx0] =================
__global__ void residual_idx(const float* __restrict__ df, const float* __restrict__ cb0,
                             const int* __restrict__ idx, float* __restrict__ res)
{
    const int row = blockIdx.x, t = threadIdx.x;
    const int id = idx[row];
    float4 v = ((const float4*)(df  + (size_t)row * 512))[t];
    float4 q = ((const float4*)(cb0 + (size_t)id  * 512))[t];
    ((float4*)(res + (size_t)row * 512))[t] =
        make_float4(v.x - q.x, v.y - q.y, v.z - q.z, v.w - q.w);
}

// ================= FFMA GEMM, BM=BN=128, 8x8 thread tile =================
// Per-output accumulation order is strictly k-ascending — BIT-IDENTICAL to the
// R1/R11-validated feature class (tiling change does not touch per-element order).
__global__ __launch_bounds__(256)
void gemm_nt(const float* __restrict__ A, int lda,
             const float* __restrict__ W, int ldw,
             const float* __restrict__ bias,
             float* __restrict__ C, int ldc, int Kin)
{
    __shared__ alignas(16) float sA[2][16][132];
    __shared__ alignas(16) float sB[2][16][132];
    __shared__ float sbias[128];
    const int tid = threadIdx.x;
    const int bm = blockIdx.y * 128;
    const int bn = blockIdx.x * 128;
    const int tx = tid & 15, ty = tid >> 4;
    const int row = tid >> 1, hk = (tid & 1) * 8;   // k offset 0 or 8 (two f4 each)
    const float* Ap = A + (size_t)(bm + row) * lda + hk;
    const float* Wp = W + (size_t)(bn + row) * ldw + hk;
    if (tid < 128) sbias[tid] = bias ? bias[bn + tid] : 0.f;

    float4 pa0 = *(const float4*)Ap,       pa1 = *(const float4*)(Ap + 4);
    float4 pb0 = *(const float4*)Wp,       pb1 = *(const float4*)(Wp + 4);
    sA[0][hk + 0][row] = pa0.x; sA[0][hk + 1][row] = pa0.y;
    sA[0][hk + 2][row] = pa0.z; sA[0][hk + 3][row] = pa0.w;
    sA[0][hk + 4][row] = pa1.x; sA[0][hk + 5][row] = pa1.y;
    sA[0][hk + 6][row] = pa1.z; sA[0][hk + 7][row] = pa1.w;
    sB[0][hk + 0][row] = pb0.x; sB[0][hk + 1][row] = pb0.y;
    sB[0][hk + 2][row] = pb0.z; sB[0][hk + 3][row] = pb0.w;
    sB[0][hk + 4][row] = pb1.x; sB[0][hk + 5][row] = pb1.y;
    sB[0][hk + 6][row] = pb1.z; sB[0][hk + 7][row] = pb1.w;
    __syncthreads();

    float acc[8][8];
#pragma unroll
    for (int i = 0; i < 8; i++)
#pragma unroll
        for (int j = 0; j < 8; j++) acc[i][j] = 0.f;

    const int nk = Kin >> 4;
    for (int t = 0; t < nk; ++t) {
        const int cur = t & 1;
        if (t + 1 < nk) {
            pa0 = *(const float4*)(Ap + (t + 1) * 16);
            pa1 = *(const float4*)(Ap + (t + 1) * 16 + 4);
            pb0 = *(const float4*)(Wp + (t + 1) * 16);
            pb1 = *(const float4*)(Wp + (t + 1) * 16 + 4);
        }
#pragma unroll
        for (int kk = 0; kk < 16; ++kk) {
            float4 fa0 = *(const float4*)&sA[cur][kk][ty << 3];
            float4 fa1 = *(const float4*)&sA[cur][kk][(ty << 3) + 4];
            float4 fb0 = *(const float4*)&sB[cur][kk][tx << 3];
            float4 fb1 = *(const float4*)&sB[cur][kk][(tx << 3) + 4];
            float av[8] = {fa0.x, fa0.y, fa0.z, fa0.w, fa1.x, fa1.y, fa1.z, fa1.w};
            float bv[8] = {fb0.x, fb0.y, fb0.z, fb0.w, fb1.x, fb1.y, fb1.z, fb1.w};
#pragma unroll
            for (int i = 0; i < 8; i++)
#pragma unroll
                for (int j = 0; j < 8; j++) acc[i][j] += av[i] * bv[j];
        }
        if (t + 1 < nk) {
            const int nxt = cur ^ 1;
            sA[nxt][hk + 0][row] = pa0.x; sA[nxt][hk + 1][row] = pa0.y;
            sA[nxt][hk + 2][row] = pa0.z; sA[nxt][hk + 3][row] = pa0.w;
            sA[nxt][hk + 4][row] = pa1.x; sA[nxt][hk + 5][row] = pa1.y;
            sA[nxt][hk + 6][row] = pa1.z; sA[nxt][hk + 7][row] = pa1.w;
            sB[nxt][hk + 0][row] = pb0.x; sB[nxt][hk + 1][row] = pb0.y;
            sB[nxt][hk + 2][row] = pb0.z; sB[nxt][hk + 3][row] = pb0.w;
            sB[nxt][hk + 4][row] = pb1.x; sB[nxt][hk + 5][row] = pb1.y;
            sB[nxt][hk + 6][row] = pb1.z; sB[nxt][hk + 7][row] = pb1.w;
        }
        __syncthreads();
    }

#pragma unroll
    for (int i = 0; i < 8; i++) {
        const int m = bm + (ty << 3) + i;
        float* Cr = C + (size_t)m * ldc + bn + (tx << 3);
        float4 v0, v1;
        v0.x = acc[i][0] + sbias[(tx << 3) + 0];
        v0.y = acc[i][1] + sbias[(tx << 3) + 1];
        v0.z = acc[i][2] + sbias[(tx << 3) + 2];
        v0.w = acc[i][3] + sbias[(tx << 3) + 3];
        v1.x = acc[i][4] + sbias[(tx << 3) + 4];
        v1.y = acc[i][5] + sbias[(tx << 3) + 5];
        v1.z = acc[i][6] + sbias[(tx << 3) + 6];
        v1.w = acc[i][7] + sbias[(tx << 3) + 7];
        *(float4*)Cr = v0;
        *(float4*)(Cr + 4) = v1;
    }
}

// ================= losses =================
__global__ __launch_bounds__(256)
void loss_kernel(const float* __restrict__ tcb, const float* __restrict__ ecb,
                 const float* __restrict__ cb0, const float* __restrict__ cb1)
{
    double s = 0.0;
    const int total = NTOK * 128;
    for (int i = blockIdx.x * 256 + threadIdx.x; i < total; i += 4096 * 256) {
        const int row = i >> 7, c = i & 127;
        float ps = 0.f;
        {
            float4 q = ((const float4*)(tcb + (size_t)g_idx[row] * 512))[c];
            float4 a = ((const float4*)(g_tf + (size_t)row * 512))[c];
            float dx = q.x - a.x, dy = q.y - a.y, dz = q.z - a.z, dw = q.w - a.w;
            ps += dx * dx + dy * dy + dz * dz + dw * dw;
        }
        {
            float4 q = ((const float4*)(ecb + (size_t)g_idx[NTOK + row] * 512))[c];
            float4 a = ((const float4*)(g_ef + (size_t)row * 512))[c];
            float dx = q.x - a.x, dy = q.y - a.y, dz = q.z - a.z, dw = q.w - a.w;
            ps += dx * dx + dy * dy + dz * dz + dw * dw;
        }
        {
            float4 q = ((const float4*)(cb0 + (size_t)g_idx[2 * NTOK + row] * 512))[c];
            float4 a = ((const float4*)(g_df + (size_t)row * 512))[c];
            float dx = q.x - a.x, dy = q.y - a.y, dz = q.z - a.z, dw = q.w - a.w;
            ps += dx * dx + dy * dy + dz * dz + dw * dw;
        }
        {
            float4 q = ((const float4*)(cb1 + (size_t)g_idx[3 * NTOK + row] * 512))[c];
            float4 a = ((const float4*)(g_res + (size_t)row * 512))[c];
            float dx = q.x - a.x, dy = q.y - a.y, dz = q.z - a.z, dw = q.w - a.w;
            ps += dx * dx + dy * dy + dz * dz + dw * dw;
        }
        s += (double)ps;
    }
    __shared__ double sh[256];
    sh[threadIdx.x] = s; __syncthreads();
    for (int o = 128; o; o >>= 1) {
        if (threadIdx.x < o) sh[threadIdx.x] += sh[threadIdx.x + o];
        __syncthreads();
    }
    if (!threadIdx.x) g_losspart[blockIdx.x] = sh[0];
}

__global__ void loss_final(float* __restrict__ out)
{
    __shared__ double sh[256];
    double s = 0.0;
    for (int i = threadIdx.x; i < 4096; i += 256) s += g_losspart[i];
    sh[threadIdx.x] = s; __syncthreads();
    for (int o = 128; o; o >>= 1) {
        if (threadIdx.x < o) sh[threadIdx.x] += sh[threadIdx.x + o];
        __syncthreads();
    }
    if (!threadIdx.x) out[0] = (float)(1.25 * sh[0] / (double)NQ);
}

// ================= output gather + idx =================
__global__ void out_gather(const float* __restrict__ outb, float* __restrict__ out)
{
    const int row = blockIdx.x, t = threadIdx.x;
    const int it = g_idx[row];
    const int ie = g_idx[NTOK + row];
    const int i0 = g_idx[2 * NTOK + row];
    const int i1 = g_idx[3 * NTOK + row];
    float4 b  = ((const float4*)outb)[t];
    float4 a0 = ((const float4*)(g_P + (size_t)it * 512))[t];
    float4 a1 = ((const float4*)(g_P + (size_t)(512  + ie) * 512))[t];
    float4 a2 = ((const float4*)(g_P + (size_t)(768  + i0) * 512))[t];
    float4 a3 = ((const float4*)(g_P + (size_t)(1280 + i1) * 512))[t];
    ((float4*)(out + (size_t)row * 512))[t] =
        make_float4(b.x + a0.x + a1.x + a2.x + a3.x,
                    b.y + a0.y + a1.y + a2.y + a3.y,
                    b.z + a0.z + a1.z + a2.z + a3.z,
                    b.w + a0.w + a1.w + a2.w + a3.w);
}

__global__ void write_idx(float* __restrict__ out)
{
    const int i = blockIdx.x * 256 + threadIdx.x;
    if (i < NTOK) {
        out[NQ + i]            = (float)g_idx[i];
        out[NQ + NTOK + i]     = (float)g_idx[NTOK + i];
        out[NQ + 2 * NTOK + i] = (float)g_idx[2 * NTOK + i];
        out[NQ + 3 * NTOK + i] = (float)g_idx[3 * NTOK + i];
    }
}

// =====================================================================
extern "C" void kernel_launch(void* const* d_in, const int* in_sizes, int n_in,
                              void* d_out, int out_size)
{
    const float* x   = (const float*)d_in[0];
    const float* tW  = (const float*)d_in[1];
    const float* tb  = (const float*)d_in[2];
    const float* eW  = (const float*)d_in[3];
    const float* eb  = (const float*)d_in[4];
    const float* dW  = (const float*)d_in[5];
    const float* db  = (const float*)d_in[6];
    const float* oW  = (const float*)d_in[7];
    const float* ob  = (const float*)d_in[8];
    const float* tcb = (const float*)d_in[9];
    const float* ecb = (const float*)d_in[10];
    const float* cb0 = (const float*)d_in[11];
    const float* cb1 = (const float*)d_in[12];
    float* out = (float*)d_out;

    void* p;
    cudaGetSymbolAddress(&p, g_tf);    float* tf    = (float*)p;
    cudaGetSymbolAddress(&p, g_ef);    float* ef    = (float*)p;
    cudaGetSymbolAddress(&p, g_df);    float* df    = (float*)p;
    cudaGetSymbolAddress(&p, g_res);   float* res   = (float*)p;
    cudaGetSymbolAddress(&p, g_fhi);   float* fhi   = (float*)p;
    cudaGetSymbolAddress(&p, g_flo);   float* flo   = (float*)p;
    cudaGetSymbolAddress(&p, g_reshi); float* reshi = (float*)p;
    cudaGetSymbolAddress(&p, g_reslo); float* reslo = (float*)p;
    cudaGetSymbolAddress(&p, g_cbhi);  float* cbhi  = (float*)p;
    cudaGetSymbolAddress(&p, g_cblo);  float* cblo  = (float*)p;
    cudaGetSymbolAddress(&p, g_sqA);   float* sqA   = (float*)p;
    cudaGetSymbolAddress(&p, g_cbsq);  float* cbsq  = (float*)p;
    cudaGetSymbolAddress(&p, g_idx);   int*   idx   = (int*)p;
    cudaGetSymbolAddress(&p, g_top2);  u64*   top2  = (u64*)p;
    cudaGetSymbolAddress(&p, g_nflag); int*   nfl   = (int*)p;
    cudaGetSymbolAddress(&p, g_flagged); int* flg   = (int*)p;
    cudaGetSymbolAddress(&p, g_P);     float* P     = (float*)p;

    cudaFuncSetAttribute(vq3t, cudaFuncAttributeMaxDynamicSharedMemorySize, GEMM_SMEM);

    // 1) codebook hi/lo decompositions + sumsq
    cvt_hilo_sq<<<64, 256>>>(tcb, cbhi,              cblo,              cbsq,        512);
    cvt_hilo_sq<<<32, 256>>>(ecb, cbhi + 512 * 512,  cblo + 512 * 512,  cbsq + 512,  256);
    cvt_hilo_sq<<<64, 256>>>(cb0, cbhi + 768 * 512,  cblo + 768 * 512,  cbsq + 768,  512);
    cvt_hilo_sq<<<64, 256>>>(cb1, cbhi + 1280 * 512, cblo + 1280 * 512, cbsq + 1280, 512);

    // 2) feature linears — FFMA GEMM, 8x8 tile (per-output k-order identical to R1)
    dim3 gFeat(4, 512);
    gemm_nt<<<gFeat, 256>>>(x, 512, tW, 512, tb, tf, 512, 512);
    gemm_nt<<<gFeat, 256>>>(x, 512, eW, 512, eb, ef, 512, 512);
    gemm_nt<<<gFeat, 256>>>(x, 512, dW, 512, db, df, 512, 512);

    // 3) feature hi/lo + row sumsq
    cvt_hilo_sq<<<8192, 256>>>(tf, fhi,          flo,          sqA,            NTOK);
    cvt_hilo_sq<<<8192, 256>>>(ef, fhi + NQ,     flo + NQ,     sqA + NTOK,     NTOK);
    cvt_hilo_sq<<<8192, 256>>>(df, fhi + 2 * NQ, flo + 2 * NQ, sqA + 2 * NTOK, NTOK);

    zero_counters<<<1, 32>>>();

    // 4) timbre: tensor VQ -> merge/flag (interval test) -> FFMA refine
    vq3t<<<dim3(2, 512), 256, GEMM_SMEM>>>(fhi, flo, cbhi, cblo, sqA, cbsq, top2);
    merge_flag<<<256, 256>>>(top2, 2, idx, flg, nfl);
    refine<<<512, 256>>>(tf, tcb, cbsq, sqA, 512, idx, flg, nfl);

    // 5) expr
    vq3t<<<dim3(1, 512), 256, GEMM_SMEM>>>(fhi + NQ, flo + NQ,
                                           cbhi + 512 * 512, cblo + 512 * 512,
                                           sqA + NTOK, cbsq + 512, top2);
    merge_flag<<<256, 256>>>(top2, 1, idx + NTOK, flg + NTOK, nfl + 1);
    refine<<<512, 256>>>(ef, ecb, cbsq + 512, sqA + NTOK, 256, idx + NTOK, flg + NTOK, nfl + 1);

    // 6) detail stage 0
    vq3t<<<dim3(2, 512), 256, GEMM_SMEM>>>(fhi + 2 * NQ, flo + 2 * NQ,
                                           cbhi + 768 * 512, cblo + 768 * 512,
                                           sqA + 2 * NTOK, cbsq + 768, top2);
    merge_flag<<<256, 256>>>(top2, 2, idx + 2 * NTOK, flg + 2 * NTOK, nfl + 2);
    refine<<<512, 256>>>(df, cb0, cbsq + 768, sqA + 2 * NTOK, 512, idx + 2 * NTOK,
                         flg + 2 * NTOK, nfl + 2);

    // 7) residual + detail stage 1
    residual_idx<<<NTOK, 128>>>(df, cb0, idx + 2 * NTOK, res);
    cvt_hilo_sq<<<8192, 256>>>(res, reshi, reslo, sqA + 3 * NTOK, NTOK);
    vq3t<<<dim3(2, 512), 256, GEMM_SMEM>>>(reshi, reslo,
                                           cbhi + 1280 * 512, cblo + 1280 * 512,
                                           sqA + 3 * NTOK, cbsq + 1280, top2);
    merge_flag<<<256, 256>>>(top2, 2, idx + 3 * NTOK, flg + 3 * NTOK, nfl + 3);
    refine<<<512, 256>>>(res, cb1, cbsq + 1280, sqA + 3 * NTOK, 512, idx + 3 * NTOK,
                         flg + 3 * NTOK, nfl + 3);

    // 8) loss
    loss_kernel<<<4096, 256>>>(tcb, ecb, cb0, cb1);
    loss_final<<<1, 256>>>(out + NQ + 4 * NTOK);

    // 9) projected codebooks (same 8x8 FFMA GEMM)
    gemm_nt<<<dim3(4, 4), 256>>>(tcb, 512, oW,        1536, nullptr, P,              512, 512);
    gemm_nt<<<dim3(4, 2), 256>>>(ecb, 512, oW + 512,  1536, nullptr, P + 512  * 512, 512, 512);
    gemm_nt<<<dim3(4, 4), 256>>>(cb0, 512, oW + 1024, 1536, nullptr, P + 768  * 512, 512, 512);
    gemm_nt<<<dim3(4, 4), 256>>>(cb1, 512, oW + 1024, 1536, nullptr, P + 1280 * 512, 512, 512);

    // 10) outputs
    out_gather<<<NTOK, 128>>>(ob, out);
    write_idx<<<256, 256>>>(out);
}